// round 8
// baseline (speedup 1.0000x reference)
#include <cuda_runtime.h>
#include <cuda_bf16.h>

// Problem constants
#define K_CODES 1024
#define DIM     64
#define N_VEC   131072          // 32*64*64 spatial vectors
#define N_ELEMS 8388608         // 32*64*64*64 output tensor elements
#define HW      4096            // H*W (stride between channel planes)
#define CHUNK   128             // codes per smem chunk
#define N_CHUNKS (K_CODES / CHUNK)
#define TPB     128
#define VPB     256             // vectors per block (2 per thread)
#define NBLK    (N_VEC / VPB)   // 512
#define CAP     48              // candidate list capacity per vector

__device__ float        g_Bk[K_CODES];
__device__ unsigned int g_embB[K_CODES * DIM / 2];   // embedding as bf16x2
__device__ double       g_part[NBLK];

__device__ __forceinline__ __nv_bfloat162 as_b162(unsigned int u) {
    return *reinterpret_cast<__nv_bfloat162*>(&u);
}

// ---- prep: Bk = sum_d e^2 (sequential fp32, bit-identical to passing kernel)
//            + embedding fp32 -> bf16x2 conversion into g_embB ----
__global__ void vq_prep(const float* __restrict__ emb) {
    __shared__ float s[32 * 65];
    const int t = threadIdx.x;
    const float4* src = (const float4*)(emb + blockIdx.x * 32 * DIM);
    unsigned int* ebq = g_embB + blockIdx.x * 32 * (DIM / 2);
#pragma unroll
    for (int j = 0; j < 16; ++j) {
        const int g = t + j * 32;            // float4 index within 32x16 tile
        float4 v = src[g];
        const int r = g >> 4;
        const int c = (g & 15) << 2;
        float* p = s + r * 65 + c;
        p[0] = v.x; p[1] = v.y; p[2] = v.z; p[3] = v.w;
        __nv_bfloat162 b0 = __floats2bfloat162_rn(v.x, v.y);
        __nv_bfloat162 b1 = __floats2bfloat162_rn(v.z, v.w);
        ebq[2 * g]     = *reinterpret_cast<unsigned int*>(&b0);
        ebq[2 * g + 1] = *reinterpret_cast<unsigned int*>(&b1);
    }
    __syncthreads();
    const float* row = s + t * 65;
    float acc = 0.0f;
#pragma unroll
    for (int d = 0; d < DIM; ++d)
        acc = __fadd_rn(acc, __fmul_rn(row[d], row[d]));
    g_Bk[blockIdx.x * 32 + t] = acc;
}

// ---- main: bf16 filter scan -> exact fp32 rescore of candidates -> output + loss ----
__global__ void __launch_bounds__(TPB, 3) vq_main(const float* __restrict__ lat,
                                                  const float* __restrict__ emb,
                                                  float* __restrict__ out) {
    __shared__ unsigned int   seb[CHUNK * DIM / 2];       // 16 KB bf16 chunk
    __shared__ float          sB[CHUNK];
    __shared__ unsigned short scand[TPB * 2 * CAP];       // 24 KB candidate lists
    __shared__ double         sred[TPB];

    const int t  = threadIdx.x;
    const int n0 = blockIdx.x * VPB + t;
    const int n1 = n0 + TPB;
    const int base0 = (n0 >> 12) * (DIM * HW) + (n0 & (HW - 1));
    const int base1 = (n1 >> 12) * (DIM * HW) + (n1 & (HW - 1));

    // ---- preamble: load x, convert to bf16x2 regs, compute |x|_1 for margin ----
    __nv_bfloat162 xb0[DIM / 2], xb1[DIM / 2];
    float l1a = 0.0f, l1b = 0.0f;
#pragma unroll
    for (int i = 0; i < DIM / 2; ++i) {
        float a = lat[base0 + (2 * i) * HW];
        float b = lat[base0 + (2 * i + 1) * HW];
        l1a += fabsf(a) + fabsf(b);
        xb0[i] = __floats2bfloat162_rn(a, b);
        float c = lat[base1 + (2 * i) * HW];
        float d = lat[base1 + (2 * i + 1) * HW];
        l1b += fabsf(c) + fabsf(d);
        xb1[i] = __floats2bfloat162_rn(c, d);
    }
    const float margin0 = 2e-5f * l1a + 5e-4f;
    const float margin1 = 2e-5f * l1b + 5e-4f;

    float best0 = -3.4e38f, best1 = -3.4e38f;   // maximize score = 2C - Bk
    int   cnt0 = 0, cnt1 = 0;
    unsigned short* lst0 = &scand[t * CAP];
    unsigned short* lst1 = &scand[(t + TPB) * CAP];

    const __nv_bfloat162 z2 = __floats2bfloat162_rn(0.0f, 0.0f);

    // ---- bf16 filter scan over all 1024 codes ----
    for (int kc = 0; kc < N_CHUNKS; ++kc) {
        __syncthreads();
        {
            const uint4* src = (const uint4*)(g_embB + kc * CHUNK * (DIM / 2));
            uint4* dst = (uint4*)seb;
#pragma unroll
            for (int j = 0; j < (CHUNK * (DIM / 2) / 4) / TPB; ++j)
                dst[t + j * TPB] = src[t + j * TPB];
            sB[t] = g_Bk[kc * CHUNK + t];
        }
        __syncthreads();

#pragma unroll 1
        for (int kk = 0; kk < CHUNK; ++kk) {
            const uint4* ep = (const uint4*)(seb + kk * (DIM / 2));
            __nv_bfloat162 a0 = z2, a1 = z2, a2 = z2, a3 = z2;
            __nv_bfloat162 b0 = z2, b1 = z2, b2 = z2, b3 = z2;
#pragma unroll
            for (int j = 0; j < 8; ++j) {
                const uint4 e = ep[j];
                const __nv_bfloat162 e0 = as_b162(e.x), e1 = as_b162(e.y);
                const __nv_bfloat162 e2 = as_b162(e.z), e3 = as_b162(e.w);
                a0 = __hfma2(xb0[4 * j],     e0, a0);
                a1 = __hfma2(xb0[4 * j + 1], e1, a1);
                a2 = __hfma2(xb0[4 * j + 2], e2, a2);
                a3 = __hfma2(xb0[4 * j + 3], e3, a3);
                b0 = __hfma2(xb1[4 * j],     e0, b0);
                b1 = __hfma2(xb1[4 * j + 1], e1, b1);
                b2 = __hfma2(xb1[4 * j + 2], e2, b2);
                b3 = __hfma2(xb1[4 * j + 3], e3, b3);
            }
            const __nv_bfloat162 h0 = __hadd2(__hadd2(a0, a1), __hadd2(a2, a3));
            const __nv_bfloat162 h1 = __hadd2(__hadd2(b0, b1), __hadd2(b2, b3));
            const float bk = sB[kk];
            const float c0 = __low2float(h0) + __high2float(h0);
            const float c1 = __low2float(h1) + __high2float(h1);
            const float s0 = __fmaf_rn(c0, 2.0f, -bk);
            const float s1 = __fmaf_rn(c1, 2.0f, -bk);

            const int k = kc * CHUNK + kk;
            if (s0 > best0 - margin0) {
                if (cnt0 < CAP) lst0[cnt0] = (unsigned short)k;
                ++cnt0;
                if (s0 > best0) best0 = s0;
            }
            if (s1 > best1 - margin1) {
                if (cnt1 < CAP) lst1[cnt1] = (unsigned short)k;
                ++cnt1;
                if (s1 > best1) best1 = s1;
            }
        }
    }

    // ---- exact fp32 rescore of candidates + straight-through output + loss ----
    // Arithmetic below is bit-identical to the passing kernel's exact path:
    //   4 scalar chains = per-lane image of the old f32x2 chains (dims mod 4),
    //   c = (s0+s1)+(s2+s3);  dist = fmaf(c,-2, fl(A+bk));  strict <, ascending k.
    double lsum = 0.0;
#pragma unroll 1
    for (int v = 0; v < 2; ++v) {
        const int base = v ? base1 : base0;
        const int cnt  = v ? cnt1  : cnt0;
        const unsigned short* lst = v ? lst1 : lst0;

        float x[DIM];
        float A = 0.0f;
#pragma unroll
        for (int i = 0; i < DIM; ++i) {
            x[i] = lat[base + i * HW];
            A = __fadd_rn(A, __fmul_rn(x[i], x[i]));   // sequential ascending: bit-identical A
        }

        float bestd = 3.4e38f;
        int   bi = 0;
        const bool overflow = (cnt > CAP);
        const int m = overflow ? K_CODES : cnt;
#pragma unroll 1
        for (int c = 0; c < m; ++c) {
            const int k = overflow ? c : (int)lst[c];
            const float* e = emb + k * DIM;
            float s0 = 0.0f, s1 = 0.0f, s2 = 0.0f, s3 = 0.0f;
#pragma unroll
            for (int j = 0; j < DIM / 4; ++j) {
                s0 = __fmaf_rn(x[4 * j],     e[4 * j],     s0);
                s1 = __fmaf_rn(x[4 * j + 1], e[4 * j + 1], s1);
                s2 = __fmaf_rn(x[4 * j + 2], e[4 * j + 2], s2);
                s3 = __fmaf_rn(x[4 * j + 3], e[4 * j + 3], s3);
            }
            const float cc = __fadd_rn(__fadd_rn(s0, s1), __fadd_rn(s2, s3));
            const float d  = __fmaf_rn(cc, -2.0f, __fadd_rn(A, g_Bk[k]));
            if (d < bestd) { bestd = d; bi = k; }      // first min (jnp.argmin)
        }

        const float* q = emb + bi * DIM;
#pragma unroll
        for (int i = 0; i < DIM; ++i) {
            const float da = __fsub_rn(q[i], x[i]);
            out[base + i * HW] = __fadd_rn(x[i], da);
            lsum += (double)__fmul_rn(da, da);
        }
    }

    // deterministic fixed-order block tree reduction (no atomics)
    sred[t] = lsum;
    __syncthreads();
#pragma unroll
    for (int s = TPB / 2; s > 0; s >>= 1) {
        if (t < s) sred[t] += sred[t + s];
        __syncthreads();
    }
    if (t == 0) g_part[blockIdx.x] = sred[0];
}

// ---- finalize: deterministic sum of block partials -> vq_loss ----
__global__ void vq_fin(float* __restrict__ out, int out_size) {
    const int t = threadIdx.x;  // 32 threads
    double s = 0.0;
    const int per = NBLK / 32;
#pragma unroll 1
    for (int i = 0; i < per; ++i) s += g_part[t * per + i];
#pragma unroll
    for (int off = 16; off > 0; off >>= 1)
        s += __shfl_down_sync(0xffffffffu, s, off);
    if (t == 0) {
        const double m  = s / (double)N_ELEMS;
        const float  mf = (float)m;
        const float loss = __fadd_rn(__fmul_rn(mf, 0.25f), mf);
        for (int i = N_ELEMS; i < out_size; ++i) out[i] = loss;
    }
}

extern "C" void kernel_launch(void* const* d_in, const int* in_sizes, int n_in,
                              void* d_out, int out_size) {
    const float* lat = (const float*)d_in[0];
    const float* emb = (const float*)d_in[1];
    if (n_in >= 2 && in_sizes[0] == K_CODES * DIM && in_sizes[1] == N_ELEMS) {
        const float* tmp = lat; lat = emb; emb = tmp;
    }
    float* out = (float*)d_out;

    vq_prep<<<K_CODES / 32, 32>>>(emb);
    vq_main<<<NBLK, TPB>>>(lat, emb, out);
    vq_fin<<<1, 32>>>(out, out_size);
}

// round 9
// speedup vs baseline: 2.8233x; 2.8233x over previous
#include <cuda_runtime.h>
#include <cuda_bf16.h>

// Problem constants
#define K_CODES 1024
#define DIM     64
#define N_VEC   131072          // 32*64*64 spatial vectors
#define N_ELEMS 8388608
#define HW      4096            // H*W (stride between channel planes)
#define TPB     256
#define ROWS_PB 128             // vectors per block
#define NBLK    (N_VEC / ROWS_PB)   // 1024
#define NTILES  8               // code tiles of 128
#define XS      37              // X smem row stride (u32 words), conflict-free
#define ES      36              // code smem row stride (u32 words), conflict-free
#define CAPR    32              // candidate capacity per row
#define MARGIN  2.5e-3f         // > 2 * worst-case bf16 score error (rigorous bound)

__device__ float        g_Bk[K_CODES];
__device__ unsigned int g_embB[K_CODES * DIM / 2];   // embedding as bf16x2 words
__device__ double       g_part[NBLK];

// ---- prep: Bk = sum_d e^2 (sequential fp32, bit-identical to passing kernels)
//            + embedding fp32 -> bf16x2 (lo = even dim) ----
__global__ void vq_prep(const float* __restrict__ emb) {
    __shared__ float s[32 * 65];
    const int t = threadIdx.x;
    const float4* src = (const float4*)(emb + blockIdx.x * 32 * DIM);
    unsigned int* ebq = g_embB + blockIdx.x * 32 * (DIM / 2);
#pragma unroll
    for (int j = 0; j < 16; ++j) {
        const int g = t + j * 32;
        float4 v = src[g];
        const int r = g >> 4;
        const int c = (g & 15) << 2;
        float* p = s + r * 65 + c;
        p[0] = v.x; p[1] = v.y; p[2] = v.z; p[3] = v.w;
        __nv_bfloat162 b0 = __floats2bfloat162_rn(v.x, v.y);
        __nv_bfloat162 b1 = __floats2bfloat162_rn(v.z, v.w);
        ebq[2 * g]     = *reinterpret_cast<unsigned int*>(&b0);
        ebq[2 * g + 1] = *reinterpret_cast<unsigned int*>(&b1);
    }
    __syncthreads();
    const float* row = s + t * 65;
    float acc = 0.0f;
#pragma unroll
    for (int d = 0; d < DIM; ++d)
        acc = __fadd_rn(acc, __fmul_rn(row[d], row[d]));
    g_Bk[blockIdx.x * 32 + t] = acc;
}

// ---- main: tensor-core bf16 scan -> margin candidates -> exact fp32 rescore ----
__global__ void __launch_bounds__(TPB, 2) vq_main(const float* __restrict__ lat,
                                                  const float* __restrict__ emb,
                                                  float* __restrict__ out) {
    __shared__ double         sred[TPB];
    __shared__ unsigned int   sX[ROWS_PB * XS];      // x bf16x2, padded
    __shared__ unsigned int   sE[128 * ES];          // code tile bf16x2, padded
    __shared__ float          sBkT[128];
    __shared__ unsigned short slist[ROWS_PB * CAPR];
    __shared__ int            scnt[ROWS_PB];

    const int tid  = threadIdx.x;
    const int warp = tid >> 5, lane = tid & 31;
    const int grp  = lane >> 2, qid = lane & 3;
    const int n0   = blockIdx.x * ROWS_PB;
    const int base = (n0 >> 12) * (DIM * HW) + (n0 & (HW - 1));

    if (tid < ROWS_PB) scnt[tid] = 0;

    // ---- stage X as bf16x2: sX[r*XS + w] = (x[r][2w], x[r][2w+1]) ----
#pragma unroll
    for (int j = 0; j < 16; ++j) {
        const int idx = j * TPB + tid;     // 4096 words
        const int w = idx >> 7, r = idx & 127;
        const float f0 = lat[base + (2 * w) * HW + r];
        const float f1 = lat[base + (2 * w + 1) * HW + r];
        __nv_bfloat162 bb = __floats2bfloat162_rn(f0, f1);
        sX[r * XS + w] = *reinterpret_cast<unsigned int*>(&bb);
    }
    __syncthreads();

    // ---- A fragments (m16n8k16 row-major): warp owns rows wrow..wrow+15 ----
    const int wrow = warp * 16;
    unsigned int a[4][4];
#pragma unroll
    for (int k = 0; k < 4; ++k) {
        a[k][0] = sX[(wrow + grp)     * XS + 8 * k + qid];       // (row,   k-lo)
        a[k][1] = sX[(wrow + grp + 8) * XS + 8 * k + qid];       // (row+8, k-lo)
        a[k][2] = sX[(wrow + grp)     * XS + 8 * k + qid + 4];   // (row,   k-hi)
        a[k][3] = sX[(wrow + grp + 8) * XS + 8 * k + qid + 4];   // (row+8, k-hi)
    }

    float acc[16][4];
#pragma unroll
    for (int nt = 0; nt < 16; ++nt) {
        acc[nt][0] = 0.0f; acc[nt][1] = 0.0f; acc[nt][2] = 0.0f; acc[nt][3] = 0.0f;
    }

    float best0 = -3.4e38f, best1 = -3.4e38f;
    const int row0 = wrow + grp, row1 = row0 + 8;

#pragma unroll 1
    for (int ct = 0; ct < NTILES; ++ct) {
        __syncthreads();   // previous tile consumed (also covers scnt init on ct=0)
        // stage code tile (128 codes) + Bk
#pragma unroll
        for (int j = 0; j < 16; ++j) {
            const int idx = j * TPB + tid;   // 4096 words
            const int c = idx >> 5, w = idx & 31;
            sE[c * ES + w] = g_embB[(ct * 128 + c) * 32 + w];
        }
        if (tid < 128) sBkT[tid] = g_Bk[ct * 128 + tid];
        __syncthreads();

        // GEMM: 16 n-tiles x 4 k-steps of m16n8k16 bf16 -> fp32
#pragma unroll
        for (int k = 0; k < 4; ++k) {
#pragma unroll
            for (int nt = 0; nt < 16; ++nt) {
                const unsigned int b0 = sE[(nt * 8 + grp) * ES + 8 * k + qid];
                const unsigned int b1 = sE[(nt * 8 + grp) * ES + 8 * k + qid + 4];
                asm volatile(
                    "mma.sync.aligned.m16n8k16.row.col.f32.bf16.bf16.f32 "
                    "{%0,%1,%2,%3}, {%4,%5,%6,%7}, {%8,%9}, {%0,%1,%2,%3};"
                    : "+f"(acc[nt][0]), "+f"(acc[nt][1]),
                      "+f"(acc[nt][2]), "+f"(acc[nt][3])
                    : "r"(a[k][0]), "r"(a[k][1]), "r"(a[k][2]), "r"(a[k][3]),
                      "r"(b0), "r"(b1));
            }
        }

        // pass 1: scores s = 2C - Bk in place, row maxima
        float tm0 = -3.4e38f, tm1 = -3.4e38f;
#pragma unroll
        for (int nt = 0; nt < 16; ++nt) {
            const float bk0 = sBkT[nt * 8 + 2 * qid];
            const float bk1 = sBkT[nt * 8 + 2 * qid + 1];
            acc[nt][0] = __fmaf_rn(acc[nt][0], 2.0f, -bk0);
            acc[nt][1] = __fmaf_rn(acc[nt][1], 2.0f, -bk1);
            acc[nt][2] = __fmaf_rn(acc[nt][2], 2.0f, -bk0);
            acc[nt][3] = __fmaf_rn(acc[nt][3], 2.0f, -bk1);
            tm0 = fmaxf(tm0, fmaxf(acc[nt][0], acc[nt][1]));
            tm1 = fmaxf(tm1, fmaxf(acc[nt][2], acc[nt][3]));
        }
        tm0 = fmaxf(tm0, __shfl_xor_sync(0xffffffffu, tm0, 1));
        tm0 = fmaxf(tm0, __shfl_xor_sync(0xffffffffu, tm0, 2));
        tm1 = fmaxf(tm1, __shfl_xor_sync(0xffffffffu, tm1, 1));
        tm1 = fmaxf(tm1, __shfl_xor_sync(0xffffffffu, tm1, 2));
        best0 = fmaxf(best0, tm0);
        best1 = fmaxf(best1, tm1);
        const float thr0 = best0 - MARGIN;   // includes this tile's max: no flood
        const float thr1 = best1 - MARGIN;

        // pass 2: append candidates, zero accumulators
#pragma unroll
        for (int nt = 0; nt < 16; ++nt) {
            const int cb = ct * 128 + nt * 8 + 2 * qid;
            if (acc[nt][0] > thr0) { int i = atomicAdd(&scnt[row0], 1); if (i < CAPR) slist[row0 * CAPR + i] = (unsigned short)cb; }
            if (acc[nt][1] > thr0) { int i = atomicAdd(&scnt[row0], 1); if (i < CAPR) slist[row0 * CAPR + i] = (unsigned short)(cb + 1); }
            if (acc[nt][2] > thr1) { int i = atomicAdd(&scnt[row1], 1); if (i < CAPR) slist[row1 * CAPR + i] = (unsigned short)cb; }
            if (acc[nt][3] > thr1) { int i = atomicAdd(&scnt[row1], 1); if (i < CAPR) slist[row1 * CAPR + i] = (unsigned short)(cb + 1); }
            acc[nt][0] = 0.0f; acc[nt][1] = 0.0f; acc[nt][2] = 0.0f; acc[nt][3] = 0.0f;
        }
    }
    __syncthreads();

    // ---- exact fp32 rescore (bit-identical arithmetic to R8's validated path) ----
    double lsum = 0.0;
    if (tid < ROWS_PB) {
        const int row = tid;
        float x[DIM];
        float A = 0.0f;
#pragma unroll
        for (int d = 0; d < DIM; ++d) {
            x[d] = lat[base + d * HW + row];
            A = __fadd_rn(A, __fmul_rn(x[d], x[d]));   // sequential ascending
        }

        float bd = 3.4e38f;
        int   bi = 0;
        const int cnt = scnt[row];
        if (cnt <= CAPR) {
#pragma unroll 1
            for (int i = 0; i < cnt; ++i) {
                const int k = (int)slist[row * CAPR + i];
                const float4* e4 = (const float4*)(emb + k * DIM);
                float s0 = 0.0f, s1 = 0.0f, s2 = 0.0f, s3 = 0.0f;
#pragma unroll
                for (int j = 0; j < DIM / 4; ++j) {
                    const float4 e = e4[j];
                    s0 = __fmaf_rn(x[4 * j],     e.x, s0);
                    s1 = __fmaf_rn(x[4 * j + 1], e.y, s1);
                    s2 = __fmaf_rn(x[4 * j + 2], e.z, s2);
                    s3 = __fmaf_rn(x[4 * j + 3], e.w, s3);
                }
                const float cc = __fadd_rn(__fadd_rn(s0, s1), __fadd_rn(s2, s3));
                const float d  = __fmaf_rn(cc, -2.0f, __fadd_rn(A, g_Bk[k]));
                // min dist, tie -> smaller k  == reference first-min
                if (d < bd || (d == bd && k < bi)) { bd = d; bi = k; }
            }
        } else {
            // overflow fallback: exact full scan, ascending k, strict <
#pragma unroll 1
            for (int k = 0; k < K_CODES; ++k) {
                const float4* e4 = (const float4*)(emb + k * DIM);
                float s0 = 0.0f, s1 = 0.0f, s2 = 0.0f, s3 = 0.0f;
#pragma unroll
                for (int j = 0; j < DIM / 4; ++j) {
                    const float4 e = e4[j];
                    s0 = __fmaf_rn(x[4 * j],     e.x, s0);
                    s1 = __fmaf_rn(x[4 * j + 1], e.y, s1);
                    s2 = __fmaf_rn(x[4 * j + 2], e.z, s2);
                    s3 = __fmaf_rn(x[4 * j + 3], e.w, s3);
                }
                const float cc = __fadd_rn(__fadd_rn(s0, s1), __fadd_rn(s2, s3));
                const float d  = __fmaf_rn(cc, -2.0f, __fadd_rn(A, g_Bk[k]));
                if (d < bd) { bd = d; bi = k; }
            }
        }

        // straight-through output + loss partial
        const float* q = emb + bi * DIM;
#pragma unroll
        for (int d = 0; d < DIM; ++d) {
            const float da = __fsub_rn(q[d], x[d]);
            out[base + d * HW + row] = __fadd_rn(x[d], da);
            lsum += (double)__fmul_rn(da, da);
        }
    }

    // deterministic fixed-order block tree reduction
    sred[tid] = lsum;
    __syncthreads();
#pragma unroll
    for (int s = TPB / 2; s > 0; s >>= 1) {
        if (tid < s) sred[tid] += sred[tid + s];
        __syncthreads();
    }
    if (tid == 0) g_part[blockIdx.x] = sred[0];
}

// ---- finalize: deterministic sum of block partials -> vq_loss ----
__global__ void vq_fin(float* __restrict__ out, int out_size) {
    const int t = threadIdx.x;  // 32 threads
    double s = 0.0;
    const int per = NBLK / 32;
#pragma unroll 1
    for (int i = 0; i < per; ++i) s += g_part[t * per + i];
#pragma unroll
    for (int off = 16; off > 0; off >>= 1)
        s += __shfl_down_sync(0xffffffffu, s, off);
    if (t == 0) {
        const double m  = s / (double)N_ELEMS;
        const float  mf = (float)m;
        const float loss = __fadd_rn(__fmul_rn(mf, 0.25f), mf);
        for (int i = N_ELEMS; i < out_size; ++i) out[i] = loss;
    }
}

extern "C" void kernel_launch(void* const* d_in, const int* in_sizes, int n_in,
                              void* d_out, int out_size) {
    const float* lat = (const float*)d_in[0];
    const float* emb = (const float*)d_in[1];
    if (n_in >= 2 && in_sizes[0] == K_CODES * DIM && in_sizes[1] == N_ELEMS) {
        const float* tmp = lat; lat = emb; emb = tmp;
    }
    float* out = (float*)d_out;

    vq_prep<<<K_CODES / 32, 32>>>(emb);
    vq_main<<<NBLK, TPB>>>(lat, emb, out);
    vq_fin<<<1, 32>>>(out, out_size);
}